// round 16
// baseline (speedup 1.0000x reference)
#include <cuda_runtime.h>
#include <cuda_bf16.h>

// WaveletTransformLayer: x (B=128, T=2048, F=32) f32.
// Per (b,f): d1 (2047) | d2 (2044) | d3 (2037) | ma3 (2037), each / T.
// Collapsed FIR taps over x[t..t+11]:
//   d1[t] = (x1-x0)/2 ; ma2 = [1,2,2,2,1]/8 ; ma3 = [1,3,5,7,8,8,8,8,7,5,3,1]/64
//   d2[t] = (x3+x4)/2 - ma2[t] ; d3[t] = ma2[t+7] - ma3[t]
//
// R16: DRAM write-granularity experiment. Block = (b, T-half, f-octet):
// owns 8 features x 1024 consecutive t (4 chunks of 256). Its 32 output
// streams are written fully sequentially (1KB/chunk, 4KB/block) instead of
// the 512B scattered chunks of all t-tiled variants (R5-R15, all ~37us at
// ~2.8TB/s with no SM counter saturated). Input: 32B sector gather per line;
// the 4 octet-blocks of a (b,half) are launch-adjacent so L2 merges sectors
// and DRAM reads each line once. 1024 blocks @ 8/SM: all resident, no waves.

#define T_LEN   2048
#define F_DIM   32
#define CH      256            // t per chunk
#define NCHUNK  4              // chunks per block (1024 t)
#define SLAB    (CH + 12)      // 268 rows incl. halo
#define PF      9              // smem row pitch (8 f + 1 pad): odd -> LDS/STS CF
#define OUT_PER_F 8165
#define SEG1    2047
#define SEG2    4091
#define SEG3    6128
#define LIM1    2047
#define LIM2    2044
#define LIM3    2037

#define NBLK    1024           // 128 b x 2 halves x 4 f-octets
#define NTHR    256

__global__ __launch_bounds__(NTHR, 8)
void wavelet_kernel(const float* __restrict__ x, float* __restrict__ out) {
    __shared__ float xs[SLAB * PF];   // 268*9*4 = 9648 B

    const int bid  = blockIdx.x;
    const int foct = bid & 3;          // f-octet 0..3 (adjacent bids share (b,half))
    const int half = (bid >> 2) & 1;   // T-half
    const int b    = bid >> 3;         // batch
    const int tid  = threadIdx.x;      // 0..255 = t within chunk

    const float* base = x + (size_t)b * (T_LEN * F_DIM) + foct * 8;
    float* outb = out + (size_t)b * (F_DIM * OUT_PER_F)
                      + (size_t)(foct * 8) * OUT_PER_F;

    const float inv   = 1.0f / 2048.0f;
    const float inv2  = inv * 0.5f;
    const float inv8  = inv * 0.125f;
    const float inv64 = inv * 0.015625f;

    #pragma unroll 1
    for (int chunk = 0; chunk < NCHUNK; ++chunk) {
        const int g0 = half * 1024 + chunk * CH;   // global t of slab row 0

        // ---- Fill: per row, 2x LDG.128 (32B sector of the line) -> 8x STS.32.
        // STS banks (9r + fi) mod 32: lane stride 9 (odd) -> conflict-free.
        #pragma unroll 1
        for (int r = tid; r < SLAB; r += NTHR) {
            int gr = g0 + r; if (gr > T_LEN - 1) gr = T_LEN - 1;  // clamp: unused
            const float4* src = (const float4*)(base + (size_t)gr * F_DIM);
            float4 a = src[0];
            float4 c = src[1];
            float* d = xs + r * PF;
            d[0] = a.x; d[1] = a.y; d[2] = a.z; d[3] = a.w;
            d[4] = c.x; d[5] = c.y; d[6] = c.z; d[7] = c.w;
        }
        __syncthreads();

        // ---- Compute: thread = t (lane-contiguous -> coalesced stores), 8 f ----
        const int tg = g0 + tid;
        const bool full = !(half == 1 && chunk == NCHUNK - 1);
        const bool w1 = full || (tg < LIM1);
        const bool w2 = full || (tg < LIM2);
        const bool w3 = full || (tg < LIM3);

        #pragma unroll 2
        for (int fi = 0; fi < 8; ++fi) {
            const float* s = xs + tid * PF + fi;   // LDS stride 9: conflict-free
            float x0  = s[0 * PF],  x1 = s[1 * PF],  x2  = s[2 * PF];
            float x3  = s[3 * PF],  x4 = s[4 * PF],  x5  = s[5 * PF];
            float x6  = s[6 * PF],  x7 = s[7 * PF],  x8  = s[8 * PF];
            float x9  = s[9 * PF], x10 = s[10 * PF], x11 = s[11 * PF];

            float d1  = (x1 - x0) * inv2;
            float m2a = x0 + x4 + 2.0f * (x1 + x2 + x3);
            float d2  = (x3 + x4) * inv2 - m2a * inv8;
            float m2b = x7 + x11 + 2.0f * (x8 + x9 + x10);
            float m3  = (x0 + x11) + 3.0f * (x1 + x10) + 5.0f * (x2 + x9)
                      + 7.0f * (x3 + x8) + 8.0f * (x4 + x5 + x6 + x7);
            float d3  = m2b * inv8 - m3 * inv64;
            float ma3 = m3 * inv64;

            float* of = outb + (size_t)fi * OUT_PER_F;
            if (w1) of[tg]        = d1;
            if (w2) of[SEG1 + tg] = d2;
            if (w3) {
                of[SEG2 + tg] = d3;
                of[SEG3 + tg] = ma3;
            }
        }
        __syncthreads();   // slab reused next chunk
    }
}

extern "C" void kernel_launch(void* const* d_in, const int* in_sizes, int n_in,
                              void* d_out, int out_size) {
    const float* x = (const float*)d_in[0];
    float* out = (float*)d_out;
    wavelet_kernel<<<NBLK, NTHR>>>(x, out);
}

// round 17
// speedup vs baseline: 1.1264x; 1.1264x over previous
#include <cuda_runtime.h>
#include <cuda_bf16.h>

// WaveletTransformLayer: x (B=128, T=2048, F=32) f32.
// Per (b,f): d1 (2047) | d2 (2044) | d3 (2037) | ma3 (2037), each / T.
// Collapsed FIR taps over x[t..t+11]:
//   d1[t] = (x1-x0)/2 ; ma2 = [1,2,2,2,1]/8 ; ma3 = [1,3,5,7,8,8,8,8,7,5,3,1]/64
//   d2[t] = (x3+x4)/2 - ma2[t] ; d3[t] = ma2[t+7] - ma3[t]
//
// R17 = R11 (best-understood variant) with st.global.wt output stores.
// Hypothesis: the ~37us plateau is L2 dirty-writeback randomization (capacity
// evictions of the 134MB output from the 126MB L2 occur in hash order, not
// program order -> poor DRAM row locality, ~4.5TB/s effective). Write-through
// sends stores to DRAM in program order (sequential-ish per stream).

#define T_LEN   2048
#define F_DIM   32
#define TT      128
#define NTILES  (T_LEN / TT)     // 16
#define NUNITS  (NTILES * 128)   // 2048
#define HALO    12
#define LOADT   (TT + HALO)      // 140
#define PITCH   33               // conflict-free for STS.32 fill and LDS.32 compute
#define OUT_PER_F 8165
#define SEG1    2047
#define SEG2    4091
#define SEG3    6128
#define LIM1    2047
#define LIM2    2044
#define LIM3    2037

#define NSM     148
#define BLKSM   3
#define GRID    (NSM * BLKSM)    // 444
#define NTHR    512

__device__ __forceinline__ void stwt(float* p, float v) {
    asm volatile("st.global.wt.f32 [%0], %1;" :: "l"(p), "f"(v) : "memory");
}

__global__ __launch_bounds__(NTHR, BLKSM)
void wavelet_kernel(const float* __restrict__ x, float* __restrict__ out) {
    __shared__ float xs[LOADT * PITCH];   // 140*33*4 = 18480 B

    const int tid = threadIdx.x;          // 0..511
    const int t   = tid & 127;            // lane-contiguous t within warp
    const int f0  = (tid >> 7) << 3;      // f-quarter base: 8 features per thread

    const float inv   = 1.0f / 2048.0f;
    const float inv2  = inv * 0.5f;
    const float inv8  = inv * 0.125f;
    const float inv64 = inv * 0.015625f;

    for (int u = blockIdx.x; u < NUNITS; u += GRID) {
        const int tile = u & (NTILES - 1);   // 0..15
        const int b    = u >> 4;             // 0..127
        const int t0   = tile * TT;

        // ---- Fill: LDG.128 (t-major, f contiguous) -> 4x STS.32, conflict-free ----
        const float4* gsrc = (const float4*)(x + (size_t)b * (T_LEN * F_DIM)
                                               + (size_t)t0 * F_DIM);
        if (tile != NTILES - 1) {
            #pragma unroll
            for (int k = 0; k < 3; ++k) {
                int i = tid + k * NTHR;
                if (i < LOADT * 8) {          // 1120 vec4s
                    int tt = i >> 3;
                    int f4 = (i & 7) << 2;
                    float4 v = gsrc[i];
                    float* d = &xs[tt * PITCH + f4];
                    d[0] = v.x; d[1] = v.y; d[2] = v.z; d[3] = v.w;
                }
            }
        } else {
            #pragma unroll
            for (int k = 0; k < 3; ++k) {
                int i = tid + k * NTHR;
                if (i < LOADT * 8) {
                    int tt = i >> 3;
                    int f4 = (i & 7) << 2;
                    float4 v = make_float4(0.f, 0.f, 0.f, 0.f);
                    if (t0 + tt < T_LEN) v = gsrc[i];
                    float* d = &xs[tt * PITCH + f4];
                    d[0] = v.x; d[1] = v.y; d[2] = v.z; d[3] = v.w;
                }
            }
        }
        __syncthreads();

        // ---- Compute: thread = t (lane-contiguous -> coalesced stores), 8 f each ----
        const int tg = t0 + t;
        float* outb = out + (size_t)b * (F_DIM * OUT_PER_F) + (size_t)f0 * OUT_PER_F;

        if (tile != NTILES - 1) {   // tiles 0..14: all stores unconditional
            #pragma unroll 2
            for (int fi = 0; fi < 8; ++fi) {
                const float* s = xs + t * PITCH + f0 + fi;
                float x0  = s[0 * PITCH],  x1 = s[1 * PITCH],  x2  = s[2 * PITCH];
                float x3  = s[3 * PITCH],  x4 = s[4 * PITCH],  x5  = s[5 * PITCH];
                float x6  = s[6 * PITCH],  x7 = s[7 * PITCH],  x8  = s[8 * PITCH];
                float x9  = s[9 * PITCH], x10 = s[10 * PITCH], x11 = s[11 * PITCH];

                float d1  = (x1 - x0) * inv2;
                float m2a = x0 + x4 + 2.0f * (x1 + x2 + x3);
                float d2  = (x3 + x4) * inv2 - m2a * inv8;
                float m2b = x7 + x11 + 2.0f * (x8 + x9 + x10);
                float m3  = (x0 + x11) + 3.0f * (x1 + x10) + 5.0f * (x2 + x9)
                          + 7.0f * (x3 + x8) + 8.0f * (x4 + x5 + x6 + x7);
                float d3  = m2b * inv8 - m3 * inv64;
                float ma3 = m3 * inv64;

                float* of = outb + (size_t)fi * OUT_PER_F;
                stwt(of + tg,        d1);
                stwt(of + SEG1 + tg, d2);
                stwt(of + SEG2 + tg, d3);
                stwt(of + SEG3 + tg, ma3);
            }
        } else {                    // tile 15: predicated stores
            const bool w1 = (tg < LIM1);
            const bool w2 = (tg < LIM2);
            const bool w3 = (tg < LIM3);
            #pragma unroll 2
            for (int fi = 0; fi < 8; ++fi) {
                const float* s = xs + t * PITCH + f0 + fi;
                float x0  = s[0 * PITCH],  x1 = s[1 * PITCH],  x2  = s[2 * PITCH];
                float x3  = s[3 * PITCH],  x4 = s[4 * PITCH],  x5  = s[5 * PITCH];
                float x6  = s[6 * PITCH],  x7 = s[7 * PITCH],  x8  = s[8 * PITCH];
                float x9  = s[9 * PITCH], x10 = s[10 * PITCH], x11 = s[11 * PITCH];

                float d1  = (x1 - x0) * inv2;
                float m2a = x0 + x4 + 2.0f * (x1 + x2 + x3);
                float d2  = (x3 + x4) * inv2 - m2a * inv8;
                float m2b = x7 + x11 + 2.0f * (x8 + x9 + x10);
                float m3  = (x0 + x11) + 3.0f * (x1 + x10) + 5.0f * (x2 + x9)
                          + 7.0f * (x3 + x8) + 8.0f * (x4 + x5 + x6 + x7);
                float d3  = m2b * inv8 - m3 * inv64;
                float ma3 = m3 * inv64;

                float* of = outb + (size_t)fi * OUT_PER_F;
                if (w1) stwt(of + tg,        d1);
                if (w2) stwt(of + SEG1 + tg, d2);
                if (w3) {
                    stwt(of + SEG2 + tg, d3);
                    stwt(of + SEG3 + tg, ma3);
                }
            }
        }
        __syncthreads();   // protect smem reuse across grid-stride iterations
    }
}

extern "C" void kernel_launch(void* const* d_in, const int* in_sizes, int n_in,
                              void* d_out, int out_size) {
    const float* x = (const float*)d_in[0];
    float* out = (float*)d_out;
    wavelet_kernel<<<GRID, NTHR>>>(x, out);
}